// round 12
// baseline (speedup 1.0000x reference)
#include <cuda_runtime.h>
#include <cuda_fp16.h>
#include <math.h>
#include <stdint.h>

// ---------------------------------------------------------------------------
// MultiHeadAttention: x@Wq/Wk/Wv -> causal flash attention -> @Wo
// B=4, S=2048, E=1024, H=16, Hs=64. fp32 I/O, FP16 tensor-core math.
// R12: x2h pre-pass eliminated. gemm_qkv reads fp32 x directly (BK=32 fp32
//      A-tiles, fragments via LDS.64 + rn pack = bit-identical to x2h path).
//      prep = weight transpose only. attn/gemm_out unchanged (at HMMA ceiling).
// ---------------------------------------------------------------------------

#define BATCH 4
#define SEQ   2048
#define EMBD  1024
#define NHEAD 16
#define HDIM  64
#define MROWS (BATCH*SEQ)   // 8192

#define QSCALE 0.18033688011112042f   // 0.125 * log2(e)

__device__ __align__(256) __half g_Q[MROWS * EMBD];
__device__ __align__(256) __half g_K[MROWS * EMBD];
__device__ __align__(256) __half g_V[MROWS * EMBD];
__device__ __align__(256) __half g_A[MROWS * EMBD];
__device__ __align__(256) __half g_W[4 * EMBD * EMBD];   // fp16, transposed [n][k]

__device__ __forceinline__ uint32_t s2u(const void* p) {
    return (uint32_t)__cvta_generic_to_shared(p);
}
#define CP16(dst, src) \
    asm volatile("cp.async.cg.shared.global [%0], [%1], 16;\n" :: "r"(dst), "l"(src))
#define CP_COMMIT()  asm volatile("cp.async.commit_group;\n" ::: "memory")
#define CP_WAIT(n)   asm volatile("cp.async.wait_group %0;\n" :: "n"(n) : "memory")

#define LDSM4(r, addr) \
    asm volatile("ldmatrix.sync.aligned.m8n8.x4.shared.b16 {%0,%1,%2,%3}, [%4];" \
        : "=r"((r)[0]), "=r"((r)[1]), "=r"((r)[2]), "=r"((r)[3]) : "r"(addr))
#define LDSM4T(r, addr) \
    asm volatile("ldmatrix.sync.aligned.m8n8.x4.trans.shared.b16 {%0,%1,%2,%3}, [%4];" \
        : "=r"((r)[0]), "=r"((r)[1]), "=r"((r)[2]), "=r"((r)[3]) : "r"(addr))

__device__ __forceinline__ void mma16(float* c, const unsigned* a, const unsigned* b) {
    asm volatile(
        "mma.sync.aligned.m16n8k16.row.col.f32.f16.f16.f32 "
        "{%0,%1,%2,%3}, {%4,%5,%6,%7}, {%8,%9}, {%0,%1,%2,%3};\n"
        : "+f"(c[0]), "+f"(c[1]), "+f"(c[2]), "+f"(c[3])
        : "r"(a[0]), "r"(a[1]), "r"(a[2]), "r"(a[3]),
          "r"(b[0]), "r"(b[1]));
}

__device__ __forceinline__ unsigned pack_h2(float lo, float hi) {
    __half2 h = __floats2half2_rn(lo, hi);
    return *(unsigned*)&h;
}

__device__ __forceinline__ float ex2f(float x) {
    float y;
    asm("ex2.approx.f32 %0, %1;" : "=f"(y) : "f"(x));
    return y;
}

__device__ __forceinline__ unsigned hex2(unsigned x) {
    unsigned y;
    asm("ex2.approx.f16x2 %0, %1;" : "=r"(y) : "r"(x));
    return y;
}

// ---------------------------------------------------------------------------
// Pre-pass: round+transpose 4 weight matrices to fp16 [n][k]
// ---------------------------------------------------------------------------
__global__ __launch_bounds__(256) void prep(
    const float* __restrict__ w0, const float* __restrict__ w1,
    const float* __restrict__ w2, const float* __restrict__ w3,
    __half* __restrict__ wout)
{
    __shared__ float t[32][33];
    const int wid = blockIdx.x;           // 0..4095
    const int z   = wid >> 10;
    const int rem = wid & 1023;
    const int bx  = (rem & 31) * 32;
    const int by  = (rem >> 5) * 32;
    const float* in = (z == 0) ? w0 : (z == 1) ? w1 : (z == 2) ? w2 : w3;
    __half* o = wout + (size_t)z * EMBD * EMBD;
    int tx = threadIdx.x & 31, ty = threadIdx.x >> 5;
    #pragma unroll
    for (int i = 0; i < 32; i += 8)
        t[ty + i][tx] = in[(size_t)(by + ty + i) * EMBD + bx + tx];
    __syncthreads();
    #pragma unroll
    for (int i = 0; i < 32; i += 8)
        o[(size_t)(bx + ty + i) * EMBD + by + tx] = __float2half_rn(t[tx][ty + i]);
}

// ---------------------------------------------------------------------------
// QKV GEMM: fp32 A direct from gmem. CTA 128x128, BK=32.
// A tile: fp32 128x32, row 128B + 16 pad (144B). Fragments via LDS.64+pack
// (same __floats2half2_rn as the old x2h pass -> bit-identical Q/K/V).
// B tile: fp16 128x32, row 64B + 16 pad (80B), LDSM conflict-free.
// 3-stage cp.async, z-fastest grid for L2 A reuse.
// ---------------------------------------------------------------------------
#define QARSTR 144
#define QBRSTR 80
#define QA_B (128 * QARSTR)            // 18432
#define QSTG (QA_B + 128 * QBRSTR)     // 28672
#define QKV_SMEM (3 * QSTG)            // 86016

__global__ __launch_bounds__(256, 2) void gemm_qkv(
    const float* __restrict__ X, const __half* __restrict__ Wt,
    __half* __restrict__ C0, __half* __restrict__ C1, __half* __restrict__ C2)
{
    extern __shared__ __align__(1024) unsigned char sgm[];

    const int z  = blockIdx.x % 3;
    const int n0 = (blockIdx.x / 3) * 128;
    const int m0 = blockIdx.y * 128;
    const __half* Bt = Wt + (size_t)z * EMBD * EMBD;
    __half* C = (z == 0) ? C0 : (z == 1) ? C1 : C2;
    const float oscale = (z == 0) ? QSCALE : 1.0f;

    const int tid  = threadIdx.x;
    const int warp = tid >> 5;
    const int lane = tid & 31;
    const int l4   = lane >> 2;
    const int lm4  = lane & 3;
    const int wm0  = (warp >> 1) * 32;
    const int wn0  = (warp & 1) * 64;

    const int lrow = lane & 15;
    const int lcol = (lane >> 4) * 16;

    float acc[2][8][4];
    #pragma unroll
    for (int mi = 0; mi < 2; mi++)
        #pragma unroll
        for (int ni = 0; ni < 8; ni++)
            #pragma unroll
            for (int q = 0; q < 4; q++) acc[mi][ni][q] = 0.0f;

    const uint32_t sbase = s2u(sgm);

    auto load_stage = [&](int s, int k0) {   // k0 in elements (fp32/fp16)
        uint32_t ab = sbase + s * QSTG;
        uint32_t bb = ab + QA_B;
        // A: 128 rows x 128B fp32 = 1024 x 16B chunks
        #pragma unroll
        for (int t = 0; t < 4; t++) {
            int id = tid + t * 256;
            int r = id >> 3;
            int cb = (id & 7) * 16;      // byte within row
            CP16(ab + r * QARSTR + cb, X + (size_t)(m0 + r) * EMBD + k0 + (cb >> 2));
        }
        // B: 128 rows x 64B fp16 = 512 x 16B chunks
        #pragma unroll
        for (int t = 0; t < 2; t++) {
            int id = tid + t * 256;
            int r = id >> 2;
            int cb = (id & 3) * 16;
            CP16(bb + r * QBRSTR + cb, Bt + (size_t)(n0 + r) * EMBD + k0 + (cb >> 1));
        }
        CP_COMMIT();
    };

    load_stage(0, 0);
    load_stage(1, 32);

    const int KT = EMBD / 32;  // 32
    for (int kt = 0; kt < KT; kt++) {
        const int s = kt % 3;
        if (kt < KT - 1) { CP_WAIT(1); } else { CP_WAIT(0); }
        __syncthreads();
        if (kt + 2 < KT) load_stage((kt + 2) % 3, (kt + 2) * 32);

        const unsigned char* ast = sgm + s * QSTG;
        const uint32_t boff = sbase + s * QSTG + QA_B
                            + (wn0 + lrow) * QBRSTR + lcol;

        #pragma unroll
        for (int kk = 0; kk < 2; kk++) {     // 2 x k16
            // A fragments from fp32 smem: rows wm0+{l4,l4+8,+16,+24},
            // k = kk*16 + lm4*2 (+8). Same rn pack as the old x2h pass.
            const int ke = kk * 16 + lm4 * 2;
            unsigned a0[4], a1[4];
            {
                const float2 v00 = *(const float2*)(ast + (wm0 + l4)      * QARSTR + ke * 4);
                const float2 v01 = *(const float2*)(ast + (wm0 + l4 + 8)  * QARSTR + ke * 4);
                const float2 v02 = *(const float2*)(ast + (wm0 + l4)      * QARSTR + (ke + 8) * 4);
                const float2 v03 = *(const float2*)(ast + (wm0 + l4 + 8)  * QARSTR + (ke + 8) * 4);
                a0[0] = pack_h2(v00.x, v00.y);
                a0[1] = pack_h2(v01.x, v01.y);
                a0[2] = pack_h2(v02.x, v02.y);
                a0[3] = pack_h2(v03.x, v03.y);
                const float2 v10 = *(const float2*)(ast + (wm0 + l4 + 16) * QARSTR + ke * 4);
                const float2 v11 = *(const float2*)(ast + (wm0 + l4 + 24) * QARSTR + ke * 4);
                const float2 v12 = *(const float2*)(ast + (wm0 + l4 + 16) * QARSTR + (ke + 8) * 4);
                const float2 v13 = *(const float2*)(ast + (wm0 + l4 + 24) * QARSTR + (ke + 8) * 4);
                a1[0] = pack_h2(v10.x, v10.y);
                a1[1] = pack_h2(v11.x, v11.y);
                a1[2] = pack_h2(v12.x, v12.y);
                a1[3] = pack_h2(v13.x, v13.y);
            }
            unsigned bf[4][4];
            #pragma unroll
            for (int ng = 0; ng < 4; ng++)
                LDSM4(bf[ng], boff + ng * 16 * QBRSTR + kk * 32);
            #pragma unroll
            for (int ni = 0; ni < 8; ni++) {
                unsigned b2[2] = { bf[ni >> 1][ni & 1], bf[ni >> 1][(ni & 1) + 2] };
                mma16(acc[0][ni], a0, b2);
                mma16(acc[1][ni], a1, b2);
            }
        }
    }

    #pragma unroll
    for (int mi = 0; mi < 2; mi++) {
        #pragma unroll
        for (int ni = 0; ni < 8; ni++) {
            int row = m0 + wm0 + mi * 16 + l4;
            int col = n0 + wn0 + ni * 8 + lm4 * 2;
            *(unsigned*)&C[(size_t)row * EMBD + col] =
                pack_h2(acc[mi][ni][0] * oscale, acc[mi][ni][1] * oscale);
            *(unsigned*)&C[(size_t)(row + 8) * EMBD + col] =
                pack_h2(acc[mi][ni][2] * oscale, acc[mi][ni][3] * oscale);
        }
    }
}

// ---------------------------------------------------------------------------
// Output GEMM (unchanged from R11): fp16 A/B, CTA 128x128, BK=64, 3-stage.
// ---------------------------------------------------------------------------
#define RSTR 144
#define TILE_B (128 * RSTR)
#define STG_BYTES (2 * TILE_B)
#define GSMEM (3 * STG_BYTES)          // 110592

__global__ __launch_bounds__(256, 2) void gemm_out(
    const __half* __restrict__ A, const __half* __restrict__ Wt, float* __restrict__ C)
{
    extern __shared__ __align__(1024) unsigned char sgm[];

    const int tid  = threadIdx.x;
    const int warp = tid >> 5;
    const int lane = tid & 31;
    const int l4   = lane >> 2;
    const int lm4  = lane & 3;
    const int wm0  = (warp >> 1) * 32;
    const int wn0  = (warp & 1) * 64;
    const int m0   = blockIdx.y * 128;
    const int n0   = blockIdx.x * 128;

    const int lrow = lane & 15;
    const int lcol = (lane >> 4) * 16;

    float acc[2][8][4];
    #pragma unroll
    for (int mi = 0; mi < 2; mi++)
        #pragma unroll
        for (int ni = 0; ni < 8; ni++)
            #pragma unroll
            for (int q = 0; q < 4; q++) acc[mi][ni][q] = 0.0f;

    const uint32_t sbase = s2u(sgm);

    auto load_stage = [&](int s, int k0) {
        uint32_t ab = sbase + s * STG_BYTES;
        uint32_t bb = ab + TILE_B;
        #pragma unroll
        for (int t = 0; t < 4; t++) {
            int id = tid + t * 256;
            int r = id >> 3;
            int c = (id & 7) * 8;
            CP16(ab + r * RSTR + c * 2, A  + (size_t)(m0 + r) * EMBD + k0 + c);
        }
        #pragma unroll
        for (int t = 0; t < 4; t++) {
            int id = tid + t * 256;
            int r = id >> 3;
            int c = (id & 7) * 8;
            CP16(bb + r * RSTR + c * 2, Wt + (size_t)(n0 + r) * EMBD + k0 + c);
        }
        CP_COMMIT();
    };

    load_stage(0, 0);
    load_stage(1, 64);

    const int KT = EMBD / 64;  // 16
    for (int kt = 0; kt < KT; kt++) {
        const int s = kt % 3;
        if (kt < KT - 1) { CP_WAIT(1); } else { CP_WAIT(0); }
        __syncthreads();
        if (kt + 2 < KT) load_stage((kt + 2) % 3, (kt + 2) * 64);

        const uint32_t ab   = sbase + s * STG_BYTES;
        const uint32_t aoff = ab + (wm0 + lrow) * RSTR + lcol;
        const uint32_t boff = ab + TILE_B + (wn0 + lrow) * RSTR + lcol;

        #pragma unroll
        for (int kk = 0; kk < 4; kk++) {
            unsigned a0[4], a1[4];
            LDSM4(a0, aoff + kk * 32);
            LDSM4(a1, aoff + 16 * RSTR + kk * 32);
            unsigned bf[4][4];
            #pragma unroll
            for (int ng = 0; ng < 4; ng++)
                LDSM4(bf[ng], boff + ng * 16 * RSTR + kk * 32);
            #pragma unroll
            for (int ni = 0; ni < 8; ni++) {
                unsigned b2[2] = { bf[ni >> 1][ni & 1], bf[ni >> 1][(ni & 1) + 2] };
                mma16(acc[0][ni], a0, b2);
                mma16(acc[1][ni], a1, b2);
            }
        }
    }

    #pragma unroll
    for (int mi = 0; mi < 2; mi++) {
        #pragma unroll
        for (int ni = 0; ni < 8; ni++) {
            int row = m0 + wm0 + mi * 16 + l4;
            int col = n0 + wn0 + ni * 8 + lm4 * 2;
            *(float2*)&C[(size_t)row * EMBD + col] =
                make_float2(acc[mi][ni][0], acc[mi][ni][1]);
            *(float2*)&C[(size_t)(row + 8) * EMBD + col] =
                make_float2(acc[mi][ni][2], acc[mi][ni][3]);
        }
    }
}

// ---------------------------------------------------------------------------
// Causal flash attention (unchanged from R11). One CTA = 128 q-rows, 128 thr
// = 4 warps x 32 q-rows. 128-key blocks per barrier pair.
// ---------------------------------------------------------------------------
#define QTB (128 * RSTR)               // 18432
#define KTB (64 * RSTR)                // 9216 per 64-key subtile
#define KVBLK (2 * KTB)                // 128-key block
#define ATTN_SMEM (QTB + 4 * KVBLK)    // 92160 bytes

__global__ __launch_bounds__(128, 2) void attn_flash(
    const __half* __restrict__ Q, const __half* __restrict__ K,
    const __half* __restrict__ V, __half* __restrict__ O)
{
    extern __shared__ __align__(1024) unsigned char sgm[];
    const uint32_t qbase = s2u(sgm);
    const uint32_t kbase = qbase + QTB;
    const uint32_t vbase = kbase + 2 * KVBLK;

    const int tid  = threadIdx.x;
    const int warp = tid >> 5;
    const int lane = tid & 31;
    const int l4   = lane >> 2;
    const int lm4  = lane & 3;
    const int w32  = warp * 32;

    const int lrow = lane & 15;
    const int lcol = (lane >> 4) * 16;

    const int qb = (gridDim.x - 1) - blockIdx.x;   // longest blocks first
    const int q0 = qb * 128;
    const int bh = blockIdx.y;
    const int b  = bh >> 4;
    const int h  = bh & 15;
    const size_t headoff = (size_t)b * SEQ * EMBD + (size_t)h * HDIM;

    const unsigned ONESH2 = 0x3C003C00u;

    #pragma unroll
    for (int t = 0; t < 8; t++) {
        int idx = tid + t * 128;
        int r = idx >> 3;
        int c = (idx & 7) * 8;
        *(uint4*)(sgm + r * RSTR + c * 2) =
            *(const uint4*)(Q + headoff + (size_t)(q0 + r) * EMBD + c);
    }

    auto load_kv2 = [&](int jj, int s) {
        #pragma unroll
        for (int t = 0; t < 8; t++) {
            int id = tid + t * 128;
            int r = id >> 3;
            int c = (id & 7) * 8;
            CP16(kbase + s * KVBLK + r * RSTR + c * 2,
                 K + headoff + (size_t)(jj * 128 + r) * EMBD + c);
        }
        #pragma unroll
        for (int t = 0; t < 8; t++) {
            int id = tid + t * 128;
            int r = id >> 3;
            int c = (id & 7) * 8;
            CP16(vbase + s * KVBLK + r * RSTR + c * 2,
                 V + headoff + (size_t)(jj * 128 + r) * EMBD + c);
        }
        CP_COMMIT();
    };

    float m[2][2] = {{-INFINITY, -INFINITY}, {-INFINITY, -INFINITY}};
    float o[2][8][4];
    float lacc[2][4];
    #pragma unroll
    for (int mi = 0; mi < 2; mi++) {
        #pragma unroll
        for (int ni = 0; ni < 8; ni++)
            #pragma unroll
            for (int q = 0; q < 4; q++) o[mi][ni][q] = 0.0f;
        #pragma unroll
        for (int q = 0; q < 4; q++) lacc[mi][q] = 0.0f;
    }

    const int njj = qb + 1;
    load_kv2(0, 0);

    const uint32_t qoff0 = qbase + (w32 + lrow) * RSTR + lcol;
    const uint32_t qoff1 = qoff0 + 16 * RSTR;

    for (int jj = 0; jj < njj; jj++) {
        CP_WAIT(0);
        __syncthreads();
        if (jj + 1 < njj) load_kv2(jj + 1, (jj + 1) & 1);

        #pragma unroll
        for (int hs = 0; hs < 2; hs++) {
            const int j = 2 * jj + hs;

            if (j * 64 > q0 + w32 + 31) continue;

            const uint32_t koff = kbase + (jj & 1) * KVBLK + hs * KTB
                                + lrow * RSTR + lcol;
            const uint32_t voff = vbase + (jj & 1) * KVBLK + hs * KTB
                                + lrow * RSTR + lcol;

            float s[2][8][4];
            #pragma unroll
            for (int mi = 0; mi < 2; mi++)
                #pragma unroll
                for (int ni = 0; ni < 8; ni++)
                    #pragma unroll
                    for (int q = 0; q < 4; q++) s[mi][ni][q] = 0.0f;

            #pragma unroll
            for (int kk = 0; kk < 4; kk++) {
                unsigned aq0[4], aq1[4];
                LDSM4(aq0, qoff0 + kk * 32);
                LDSM4(aq1, qoff1 + kk * 32);
                unsigned bf[4][4];
                #pragma unroll
                for (int ng = 0; ng < 4; ng++)
                    LDSM4(bf[ng], koff + ng * 16 * RSTR + kk * 32);
                #pragma unroll
                for (int ni = 0; ni < 8; ni++) {
                    unsigned b2[2] = { bf[ni >> 1][ni & 1], bf[ni >> 1][(ni & 1) + 2] };
                    mma16(s[0][ni], aq0, b2);
                    mma16(s[1][ni], aq1, b2);
                }
            }

            if (j * 64 + 63 > q0 + w32) {
                #pragma unroll
                for (int mi = 0; mi < 2; mi++) {
                    const int g0 = q0 + w32 + mi * 16 + l4;
                    const int g1 = g0 + 8;
                    #pragma unroll
                    for (int ni = 0; ni < 8; ni++) {
                        int gc = j * 64 + ni * 8 + lm4 * 2;
                        if (gc     > g0) s[mi][ni][0] = -INFINITY;
                        if (gc + 1 > g0) s[mi][ni][1] = -INFINITY;
                        if (gc     > g1) s[mi][ni][2] = -INFINITY;
                        if (gc + 1 > g1) s[mi][ni][3] = -INFINITY;
                    }
                }
            }

            float a[2][2], nm[2][2];
            #pragma unroll
            for (int mi = 0; mi < 2; mi++) {
                float rm0 = -INFINITY, rm1 = -INFINITY;
                #pragma unroll
                for (int ni = 0; ni < 8; ni++) {
                    rm0 = fmaxf(rm0, fmaxf(s[mi][ni][0], s[mi][ni][1]));
                    rm1 = fmaxf(rm1, fmaxf(s[mi][ni][2], s[mi][ni][3]));
                }
                #pragma unroll
                for (int off = 1; off < 4; off <<= 1) {
                    rm0 = fmaxf(rm0, __shfl_xor_sync(0xffffffffu, rm0, off));
                    rm1 = fmaxf(rm1, __shfl_xor_sync(0xffffffffu, rm1, off));
                }
                nm[mi][0] = fmaxf(m[mi][0], rm0);
                nm[mi][1] = fmaxf(m[mi][1], rm1);
                a[mi][0] = ex2f(m[mi][0] - nm[mi][0]);
                a[mi][1] = ex2f(m[mi][1] - nm[mi][1]);
                m[mi][0] = nm[mi][0];
                m[mi][1] = nm[mi][1];
            }

            bool noresc = (a[0][0] == 1.0f) && (a[0][1] == 1.0f)
                       && (a[1][0] == 1.0f) && (a[1][1] == 1.0f);
            if (!__all_sync(0xffffffffu, noresc)) {
                #pragma unroll
                for (int mi = 0; mi < 2; mi++) {
                    #pragma unroll
                    for (int ni = 0; ni < 8; ni++) {
                        o[mi][ni][0] *= a[mi][0]; o[mi][ni][1] *= a[mi][0];
                        o[mi][ni][2] *= a[mi][1]; o[mi][ni][3] *= a[mi][1];
                    }
                    lacc[mi][0] *= a[mi][0]; lacc[mi][1] *= a[mi][0];
                    lacc[mi][2] *= a[mi][1]; lacc[mi][3] *= a[mi][1];
                }
            }

            #pragma unroll
            for (int g = 0; g < 4; g++) {
                unsigned ap[2][4];
                #pragma unroll
                for (int mi = 0; mi < 2; mi++) {
                    ap[mi][0] = hex2(pack_h2(s[mi][2*g][0]   - nm[mi][0],
                                             s[mi][2*g][1]   - nm[mi][0]));
                    ap[mi][1] = hex2(pack_h2(s[mi][2*g][2]   - nm[mi][1],
                                             s[mi][2*g][3]   - nm[mi][1]));
                    ap[mi][2] = hex2(pack_h2(s[mi][2*g+1][0] - nm[mi][0],
                                             s[mi][2*g+1][1] - nm[mi][0]));
                    ap[mi][3] = hex2(pack_h2(s[mi][2*g+1][2] - nm[mi][1],
                                             s[mi][2*g+1][3] - nm[mi][1]));
                }

                unsigned ones2[2] = { ONESH2, ONESH2 };
                mma16(lacc[0], ap[0], ones2);
                mma16(lacc[1], ap[1], ones2);

                #pragma unroll
                for (int dg = 0; dg < 4; dg++) {
                    unsigned vf[4];
                    LDSM4T(vf, voff + g * 16 * RSTR + dg * 32);
                    unsigned b0[2] = { vf[0], vf[1] };
                    unsigned b1[2] = { vf[2], vf[3] };
                    mma16(o[0][2*dg],     ap[0], b0);
                    mma16(o[0][2*dg + 1], ap[0], b1);
                    mma16(o[1][2*dg],     ap[1], b0);
                    mma16(o[1][2*dg + 1], ap[1], b1);
                }
            }
        }
    }

    #pragma unroll
    for (int mi = 0; mi < 2; mi++) {
        float i0 = 1.0f / lacc[mi][0];
        float i1 = 1.0f / lacc[mi][2];
        #pragma unroll
        for (int ni = 0; ni < 8; ni++) {
            int gr = b * SEQ + q0 + w32 + mi * 16 + l4;
            int gc = h * HDIM + ni * 8 + lm4 * 2;
            *(unsigned*)&O[(size_t)gr * EMBD + gc] =
                pack_h2(o[mi][ni][0] * i0, o[mi][ni][1] * i0);
            *(unsigned*)&O[(size_t)(gr + 8) * EMBD + gc] =
                pack_h2(o[mi][ni][2] * i1, o[mi][ni][3] * i1);
        }
    }
}

// ---------------------------------------------------------------------------
// Launch
// ---------------------------------------------------------------------------
extern "C" void kernel_launch(void* const* d_in, const int* in_sizes, int n_in,
                              void* d_out, int out_size)
{
    const float* x  = (const float*)d_in[0];
    const float* Wq = (const float*)d_in[1];
    const float* Wk = (const float*)d_in[2];
    const float* Wv = (const float*)d_in[3];
    const float* Wo = (const float*)d_in[4];
    float* out = (float*)d_out;

    __half *Qp, *Kp, *Vp, *Ap, *Wp;
    cudaGetSymbolAddress((void**)&Qp, g_Q);
    cudaGetSymbolAddress((void**)&Kp, g_K);
    cudaGetSymbolAddress((void**)&Vp, g_V);
    cudaGetSymbolAddress((void**)&Ap, g_A);
    cudaGetSymbolAddress((void**)&Wp, g_W);

    cudaFuncSetAttribute(gemm_qkv,   cudaFuncAttributeMaxDynamicSharedMemorySize, QKV_SMEM);
    cudaFuncSetAttribute(gemm_out,   cudaFuncAttributeMaxDynamicSharedMemorySize, GSMEM);
    cudaFuncSetAttribute(attn_flash, cudaFuncAttributeMaxDynamicSharedMemorySize, ATTN_SMEM);

    prep<<<4096, 256>>>(Wq, Wk, Wv, Wo, Wp);

    dim3 gqkv((EMBD / 128) * 3, MROWS / 128);   // (24, 64), z fastest
    gemm_qkv<<<gqkv, 256, QKV_SMEM>>>(x, Wp, Qp, Kp, Vp);

    dim3 ga(SEQ / 128, BATCH * NHEAD);          // (16, 64)
    attn_flash<<<ga, 128, ATTN_SMEM>>>(Qp, Kp, Vp, Ap);

    dim3 go(EMBD / 128, MROWS / 128);
    gemm_out<<<go, 256, GSMEM>>>(Ap, Wp + 3 * (size_t)EMBD * EMBD, out);
}

// round 13
// speedup vs baseline: 1.1688x; 1.1688x over previous
#include <cuda_runtime.h>
#include <cuda_fp16.h>
#include <math.h>
#include <stdint.h>

// ---------------------------------------------------------------------------
// MultiHeadAttention: x@Wq/Wk/Wv -> causal flash attention -> @Wo
// B=4, S=2048, E=1024, H=16, Hs=64. fp32 I/O, FP16 tensor-core math.
// R13: revert R12 (fp32-A qkv regressed). R11 structure + Q fragments hoisted
//      to registers in attention (removes 20% of smem traffic: Q re-LDSM
//      per subtile was loop-invariant).
// ---------------------------------------------------------------------------

#define BATCH 4
#define SEQ   2048
#define EMBD  1024
#define NHEAD 16
#define HDIM  64
#define MROWS (BATCH*SEQ)   // 8192

#define QSCALE 0.18033688011112042f   // 0.125 * log2(e)

__device__ __align__(256) __half g_Q[MROWS * EMBD];
__device__ __align__(256) __half g_K[MROWS * EMBD];
__device__ __align__(256) __half g_V[MROWS * EMBD];
__device__ __align__(256) __half g_A[MROWS * EMBD];
__device__ __align__(256) __half g_X[MROWS * EMBD];
__device__ __align__(256) __half g_W[4 * EMBD * EMBD];   // fp16, transposed [n][k]

__device__ __forceinline__ uint32_t s2u(const void* p) {
    return (uint32_t)__cvta_generic_to_shared(p);
}
#define CP16(dst, src) \
    asm volatile("cp.async.cg.shared.global [%0], [%1], 16;\n" :: "r"(dst), "l"(src))
#define CP_COMMIT()  asm volatile("cp.async.commit_group;\n" ::: "memory")
#define CP_WAIT(n)   asm volatile("cp.async.wait_group %0;\n" :: "n"(n) : "memory")

#define LDSM4(r, addr) \
    asm volatile("ldmatrix.sync.aligned.m8n8.x4.shared.b16 {%0,%1,%2,%3}, [%4];" \
        : "=r"((r)[0]), "=r"((r)[1]), "=r"((r)[2]), "=r"((r)[3]) : "r"(addr))
#define LDSM4T(r, addr) \
    asm volatile("ldmatrix.sync.aligned.m8n8.x4.trans.shared.b16 {%0,%1,%2,%3}, [%4];" \
        : "=r"((r)[0]), "=r"((r)[1]), "=r"((r)[2]), "=r"((r)[3]) : "r"(addr))

__device__ __forceinline__ void mma16(float* c, const unsigned* a, const unsigned* b) {
    asm volatile(
        "mma.sync.aligned.m16n8k16.row.col.f32.f16.f16.f32 "
        "{%0,%1,%2,%3}, {%4,%5,%6,%7}, {%8,%9}, {%0,%1,%2,%3};\n"
        : "+f"(c[0]), "+f"(c[1]), "+f"(c[2]), "+f"(c[3])
        : "r"(a[0]), "r"(a[1]), "r"(a[2]), "r"(a[3]),
          "r"(b[0]), "r"(b[1]));
}

__device__ __forceinline__ unsigned pack_h2(float lo, float hi) {
    __half2 h = __floats2half2_rn(lo, hi);
    return *(unsigned*)&h;
}

__device__ __forceinline__ float ex2f(float x) {
    float y;
    asm("ex2.approx.f32 %0, %1;" : "=f"(y) : "f"(x));
    return y;
}

__device__ __forceinline__ unsigned hex2(unsigned x) {
    unsigned y;
    asm("ex2.approx.f16x2 %0, %1;" : "=r"(y) : "r"(x));
    return y;
}

// ---------------------------------------------------------------------------
// Merged pre-pass: blocks [0,8192) convert x -> fp16; blocks [8192,12288)
// round+transpose the 4 weight matrices to fp16 [n][k].
// ---------------------------------------------------------------------------
#define XBLKS 8192
__global__ __launch_bounds__(256) void prep(
    const float4* __restrict__ x, uint2* __restrict__ xout,
    const float* __restrict__ w0, const float* __restrict__ w1,
    const float* __restrict__ w2, const float* __restrict__ w3,
    __half* __restrict__ wout)
{
    __shared__ float t[32][33];
    const int bid = blockIdx.x;
    if (bid < XBLKS) {
        int i = bid * 256 + threadIdx.x;
        float4 v = x[i];
        xout[i] = make_uint2(pack_h2(v.x, v.y), pack_h2(v.z, v.w));
    } else {
        const int wid = bid - XBLKS;
        const int z   = wid >> 10;
        const int rem = wid & 1023;
        const int bx  = (rem & 31) * 32;
        const int by  = (rem >> 5) * 32;
        const float* in = (z == 0) ? w0 : (z == 1) ? w1 : (z == 2) ? w2 : w3;
        __half* o = wout + (size_t)z * EMBD * EMBD;
        int tx = threadIdx.x & 31, ty = threadIdx.x >> 5;
        #pragma unroll
        for (int i = 0; i < 32; i += 8)
            t[ty + i][tx] = in[(size_t)(by + ty + i) * EMBD + bx + tx];
        __syncthreads();
        #pragma unroll
        for (int i = 0; i < 32; i += 8)
            o[(size_t)(bx + ty + i) * EMBD + by + tx] = __float2half_rn(t[tx][ty + i]);
    }
}

// ---------------------------------------------------------------------------
// FP16 GEMM body. CTA 128x128, BK=64, 3-stage cp.async, LDSM fragments.
// ---------------------------------------------------------------------------
#define RSTR 144
#define TILE_B (128 * RSTR)
#define STG_BYTES (2 * TILE_B)
#define GST 3
#define GSMEM (GST * STG_BYTES)        // 110592

template<bool HALF_OUT>
__device__ __forceinline__ void gemm_body(
    const __half* __restrict__ A, const __half* __restrict__ Bt, void* __restrict__ Cv,
    float oscale, int m0, int n0)
{
    extern __shared__ __align__(1024) unsigned char sgm[];

    const int tid  = threadIdx.x;
    const int warp = tid >> 5;
    const int lane = tid & 31;
    const int l4   = lane >> 2;
    const int lm4  = lane & 3;
    const int wm0  = (warp >> 1) * 32;
    const int wn0  = (warp & 1) * 64;

    const int lrow = lane & 15;
    const int lcol = (lane >> 4) * 16;

    float acc[2][8][4];
    #pragma unroll
    for (int mi = 0; mi < 2; mi++)
        #pragma unroll
        for (int ni = 0; ni < 8; ni++)
            #pragma unroll
            for (int q = 0; q < 4; q++) acc[mi][ni][q] = 0.0f;

    const uint32_t sbase = s2u(sgm);

    auto load_stage = [&](int s, int k0) {
        uint32_t ab = sbase + s * STG_BYTES;
        uint32_t bb = ab + TILE_B;
        #pragma unroll
        for (int t = 0; t < 4; t++) {
            int id = tid + t * 256;
            int r = id >> 3;
            int c = (id & 7) * 8;
            CP16(ab + r * RSTR + c * 2, A  + (size_t)(m0 + r) * EMBD + k0 + c);
        }
        #pragma unroll
        for (int t = 0; t < 4; t++) {
            int id = tid + t * 256;
            int r = id >> 3;
            int c = (id & 7) * 8;
            CP16(bb + r * RSTR + c * 2, Bt + (size_t)(n0 + r) * EMBD + k0 + c);
        }
        CP_COMMIT();
    };

    load_stage(0, 0);
    load_stage(1, 64);

    const int KT = EMBD / 64;  // 16
    for (int kt = 0; kt < KT; kt++) {
        const int s = kt % GST;
        if (kt < KT - 1) { CP_WAIT(1); } else { CP_WAIT(0); }
        __syncthreads();
        if (kt + 2 < KT) load_stage((kt + 2) % GST, (kt + 2) * 64);

        const uint32_t ab   = sbase + s * STG_BYTES;
        const uint32_t aoff = ab + (wm0 + lrow) * RSTR + lcol;
        const uint32_t boff = ab + TILE_B + (wn0 + lrow) * RSTR + lcol;

        #pragma unroll
        for (int kk = 0; kk < 4; kk++) {
            unsigned a0[4], a1[4];
            LDSM4(a0, aoff + kk * 32);
            LDSM4(a1, aoff + 16 * RSTR + kk * 32);
            unsigned bf[4][4];
            #pragma unroll
            for (int ng = 0; ng < 4; ng++)
                LDSM4(bf[ng], boff + ng * 16 * RSTR + kk * 32);
            #pragma unroll
            for (int ni = 0; ni < 8; ni++) {
                unsigned b2[2] = { bf[ni >> 1][ni & 1], bf[ni >> 1][(ni & 1) + 2] };
                mma16(acc[0][ni], a0, b2);
                mma16(acc[1][ni], a1, b2);
            }
        }
    }

    #pragma unroll
    for (int mi = 0; mi < 2; mi++) {
        #pragma unroll
        for (int ni = 0; ni < 8; ni++) {
            int row = m0 + wm0 + mi * 16 + l4;
            int col = n0 + wn0 + ni * 8 + lm4 * 2;
            if (HALF_OUT) {
                __half* C = (__half*)Cv;
                *(unsigned*)&C[(size_t)row * EMBD + col] =
                    pack_h2(acc[mi][ni][0] * oscale, acc[mi][ni][1] * oscale);
                *(unsigned*)&C[(size_t)(row + 8) * EMBD + col] =
                    pack_h2(acc[mi][ni][2] * oscale, acc[mi][ni][3] * oscale);
            } else {
                float* C = (float*)Cv;
                *(float2*)&C[(size_t)row * EMBD + col] =
                    make_float2(acc[mi][ni][0], acc[mi][ni][1]);
                *(float2*)&C[(size_t)(row + 8) * EMBD + col] =
                    make_float2(acc[mi][ni][2], acc[mi][ni][3]);
            }
        }
    }
}

__global__ __launch_bounds__(256, 2) void gemm_qkv(
    const __half* __restrict__ X, const __half* __restrict__ Wt,
    __half* __restrict__ C0, __half* __restrict__ C1, __half* __restrict__ C2)
{
    const int z  = blockIdx.x % 3;
    const int n0 = (blockIdx.x / 3) * 128;
    const int m0 = blockIdx.y * 128;
    const __half* Bt = Wt + (size_t)z * EMBD * EMBD;
    __half* C = (z == 0) ? C0 : (z == 1) ? C1 : C2;
    float sc = (z == 0) ? QSCALE : 1.0f;
    gemm_body<true>(X, Bt, C, sc, m0, n0);
}

__global__ __launch_bounds__(256, 2) void gemm_out(
    const __half* __restrict__ A, const __half* __restrict__ Wt, float* __restrict__ C)
{
    gemm_body<false>(A, Wt, C, 1.0f, blockIdx.y * 128, blockIdx.x * 128);
}

// ---------------------------------------------------------------------------
// Causal flash attention. One CTA = 128 q-rows of one (b,h), 128 threads =
// 4 warps x 32 q-rows. 128-key blocks per barrier pair. Q fragments hoisted
// to registers (loop-invariant; removes 8 LDSM.x4/warp/subtile).
// ---------------------------------------------------------------------------
#define QTB (128 * RSTR)               // 18432
#define KTB (64 * RSTR)                // 9216 per 64-key subtile
#define KVBLK (2 * KTB)                // 128-key block
#define ATTN_SMEM (QTB + 4 * KVBLK)    // 92160 bytes

__global__ __launch_bounds__(128, 2) void attn_flash(
    const __half* __restrict__ Q, const __half* __restrict__ K,
    const __half* __restrict__ V, __half* __restrict__ O)
{
    extern __shared__ __align__(1024) unsigned char sgm[];
    const uint32_t qbase = s2u(sgm);
    const uint32_t kbase = qbase + QTB;
    const uint32_t vbase = kbase + 2 * KVBLK;

    const int tid  = threadIdx.x;
    const int warp = tid >> 5;
    const int lane = tid & 31;
    const int l4   = lane >> 2;
    const int lm4  = lane & 3;
    const int w32  = warp * 32;

    const int lrow = lane & 15;
    const int lcol = (lane >> 4) * 16;

    const int qb = (gridDim.x - 1) - blockIdx.x;   // longest blocks first
    const int q0 = qb * 128;
    const int bh = blockIdx.y;
    const int b  = bh >> 4;
    const int h  = bh & 15;
    const size_t headoff = (size_t)b * SEQ * EMBD + (size_t)h * HDIM;

    const unsigned ONESH2 = 0x3C003C00u;

    // Load Q tile (128 x 64 fp16)
    #pragma unroll
    for (int t = 0; t < 8; t++) {
        int idx = tid + t * 128;
        int r = idx >> 3;
        int c = (idx & 7) * 8;
        *(uint4*)(sgm + r * RSTR + c * 2) =
            *(const uint4*)(Q + headoff + (size_t)(q0 + r) * EMBD + c);
    }

    auto load_kv2 = [&](int jj, int s) {
        #pragma unroll
        for (int t = 0; t < 8; t++) {
            int id = tid + t * 128;
            int r = id >> 3;
            int c = (id & 7) * 8;
            CP16(kbase + s * KVBLK + r * RSTR + c * 2,
                 K + headoff + (size_t)(jj * 128 + r) * EMBD + c);
        }
        #pragma unroll
        for (int t = 0; t < 8; t++) {
            int id = tid + t * 128;
            int r = id >> 3;
            int c = (id & 7) * 8;
            CP16(vbase + s * KVBLK + r * RSTR + c * 2,
                 V + headoff + (size_t)(jj * 128 + r) * EMBD + c);
        }
        CP_COMMIT();
    };

    float m[2][2] = {{-INFINITY, -INFINITY}, {-INFINITY, -INFINITY}};
    float o[2][8][4];
    float lacc[2][4];
    #pragma unroll
    for (int mi = 0; mi < 2; mi++) {
        #pragma unroll
        for (int ni = 0; ni < 8; ni++)
            #pragma unroll
            for (int q = 0; q < 4; q++) o[mi][ni][q] = 0.0f;
        #pragma unroll
        for (int q = 0; q < 4; q++) lacc[mi][q] = 0.0f;
    }

    const int njj = qb + 1;
    load_kv2(0, 0);

    // Hoist Q fragments into registers (loop-invariant across all subtiles)
    __syncthreads();
    unsigned qf[2][4][4];   // [mi][kk][frag]
    {
        const uint32_t qoff0 = qbase + (w32 + lrow) * RSTR + lcol;
        const uint32_t qoff1 = qoff0 + 16 * RSTR;
        #pragma unroll
        for (int kk = 0; kk < 4; kk++) {
            LDSM4(qf[0][kk], qoff0 + kk * 32);
            LDSM4(qf[1][kk], qoff1 + kk * 32);
        }
    }

    for (int jj = 0; jj < njj; jj++) {
        CP_WAIT(0);
        __syncthreads();
        if (jj + 1 < njj) load_kv2(jj + 1, (jj + 1) & 1);

        #pragma unroll
        for (int hs = 0; hs < 2; hs++) {
            const int j = 2 * jj + hs;

            if (j * 64 > q0 + w32 + 31) continue;

            const uint32_t koff = kbase + (jj & 1) * KVBLK + hs * KTB
                                + lrow * RSTR + lcol;
            const uint32_t voff = vbase + (jj & 1) * KVBLK + hs * KTB
                                + lrow * RSTR + lcol;

            // S = Q K^T (warp: 32 q-rows x 64 keys)
            float s[2][8][4];
            #pragma unroll
            for (int mi = 0; mi < 2; mi++)
                #pragma unroll
                for (int ni = 0; ni < 8; ni++)
                    #pragma unroll
                    for (int q = 0; q < 4; q++) s[mi][ni][q] = 0.0f;

            #pragma unroll
            for (int kk = 0; kk < 4; kk++) {
                unsigned bf[4][4];
                #pragma unroll
                for (int ng = 0; ng < 4; ng++)
                    LDSM4(bf[ng], koff + ng * 16 * RSTR + kk * 32);
                #pragma unroll
                for (int ni = 0; ni < 8; ni++) {
                    unsigned b2[2] = { bf[ni >> 1][ni & 1], bf[ni >> 1][(ni & 1) + 2] };
                    mma16(s[0][ni], qf[0][kk], b2);
                    mma16(s[1][ni], qf[1][kk], b2);
                }
            }

            // Causal mask (diag subtiles only; warp-uniform)
            if (j * 64 + 63 > q0 + w32) {
                #pragma unroll
                for (int mi = 0; mi < 2; mi++) {
                    const int g0 = q0 + w32 + mi * 16 + l4;
                    const int g1 = g0 + 8;
                    #pragma unroll
                    for (int ni = 0; ni < 8; ni++) {
                        int gc = j * 64 + ni * 8 + lm4 * 2;
                        if (gc     > g0) s[mi][ni][0] = -INFINITY;
                        if (gc + 1 > g0) s[mi][ni][1] = -INFINITY;
                        if (gc     > g1) s[mi][ni][2] = -INFINITY;
                        if (gc + 1 > g1) s[mi][ni][3] = -INFINITY;
                    }
                }
            }

            // Row max + online rescale (per mfrag, per half)
            float a[2][2], nm[2][2];
            #pragma unroll
            for (int mi = 0; mi < 2; mi++) {
                float rm0 = -INFINITY, rm1 = -INFINITY;
                #pragma unroll
                for (int ni = 0; ni < 8; ni++) {
                    rm0 = fmaxf(rm0, fmaxf(s[mi][ni][0], s[mi][ni][1]));
                    rm1 = fmaxf(rm1, fmaxf(s[mi][ni][2], s[mi][ni][3]));
                }
                #pragma unroll
                for (int off = 1; off < 4; off <<= 1) {
                    rm0 = fmaxf(rm0, __shfl_xor_sync(0xffffffffu, rm0, off));
                    rm1 = fmaxf(rm1, __shfl_xor_sync(0xffffffffu, rm1, off));
                }
                nm[mi][0] = fmaxf(m[mi][0], rm0);
                nm[mi][1] = fmaxf(m[mi][1], rm1);
                a[mi][0] = ex2f(m[mi][0] - nm[mi][0]);
                a[mi][1] = ex2f(m[mi][1] - nm[mi][1]);
                m[mi][0] = nm[mi][0];
                m[mi][1] = nm[mi][1];
            }

            bool noresc = (a[0][0] == 1.0f) && (a[0][1] == 1.0f)
                       && (a[1][0] == 1.0f) && (a[1][1] == 1.0f);
            if (!__all_sync(0xffffffffu, noresc)) {
                #pragma unroll
                for (int mi = 0; mi < 2; mi++) {
                    #pragma unroll
                    for (int ni = 0; ni < 8; ni++) {
                        o[mi][ni][0] *= a[mi][0]; o[mi][ni][1] *= a[mi][0];
                        o[mi][ni][2] *= a[mi][1]; o[mi][ni][3] *= a[mi][1];
                    }
                    lacc[mi][0] *= a[mi][0]; lacc[mi][1] *= a[mi][0];
                    lacc[mi][2] *= a[mi][1]; lacc[mi][3] *= a[mi][1];
                }
            }

            // P = 2^(s-m) via packed f16x2 ex2; O += P@V; l += P@1
            #pragma unroll
            for (int g = 0; g < 4; g++) {
                unsigned ap[2][4];
                #pragma unroll
                for (int mi = 0; mi < 2; mi++) {
                    ap[mi][0] = hex2(pack_h2(s[mi][2*g][0]   - nm[mi][0],
                                             s[mi][2*g][1]   - nm[mi][0]));
                    ap[mi][1] = hex2(pack_h2(s[mi][2*g][2]   - nm[mi][1],
                                             s[mi][2*g][3]   - nm[mi][1]));
                    ap[mi][2] = hex2(pack_h2(s[mi][2*g+1][0] - nm[mi][0],
                                             s[mi][2*g+1][1] - nm[mi][0]));
                    ap[mi][3] = hex2(pack_h2(s[mi][2*g+1][2] - nm[mi][1],
                                             s[mi][2*g+1][3] - nm[mi][1]));
                }

                unsigned ones2[2] = { ONESH2, ONESH2 };
                mma16(lacc[0], ap[0], ones2);
                mma16(lacc[1], ap[1], ones2);

                #pragma unroll
                for (int dg = 0; dg < 4; dg++) {
                    unsigned vf[4];
                    LDSM4T(vf, voff + g * 16 * RSTR + dg * 32);
                    unsigned b0[2] = { vf[0], vf[1] };
                    unsigned b1[2] = { vf[2], vf[3] };
                    mma16(o[0][2*dg],     ap[0], b0);
                    mma16(o[0][2*dg + 1], ap[0], b1);
                    mma16(o[1][2*dg],     ap[1], b0);
                    mma16(o[1][2*dg + 1], ap[1], b1);
                }
            }
        }
    }

    // Epilogue
    #pragma unroll
    for (int mi = 0; mi < 2; mi++) {
        float i0 = 1.0f / lacc[mi][0];
        float i1 = 1.0f / lacc[mi][2];
        #pragma unroll
        for (int ni = 0; ni < 8; ni++) {
            int gr = b * SEQ + q0 + w32 + mi * 16 + l4;
            int gc = h * HDIM + ni * 8 + lm4 * 2;
            *(unsigned*)&O[(size_t)gr * EMBD + gc] =
                pack_h2(o[mi][ni][0] * i0, o[mi][ni][1] * i0);
            *(unsigned*)&O[(size_t)(gr + 8) * EMBD + gc] =
                pack_h2(o[mi][ni][2] * i1, o[mi][ni][3] * i1);
        }
    }
}

// ---------------------------------------------------------------------------
// Launch
// ---------------------------------------------------------------------------
extern "C" void kernel_launch(void* const* d_in, const int* in_sizes, int n_in,
                              void* d_out, int out_size)
{
    const float* x  = (const float*)d_in[0];
    const float* Wq = (const float*)d_in[1];
    const float* Wk = (const float*)d_in[2];
    const float* Wv = (const float*)d_in[3];
    const float* Wo = (const float*)d_in[4];
    float* out = (float*)d_out;

    __half *Qp, *Kp, *Vp, *Ap, *Xp, *Wp;
    cudaGetSymbolAddress((void**)&Qp, g_Q);
    cudaGetSymbolAddress((void**)&Kp, g_K);
    cudaGetSymbolAddress((void**)&Vp, g_V);
    cudaGetSymbolAddress((void**)&Ap, g_A);
    cudaGetSymbolAddress((void**)&Xp, g_X);
    cudaGetSymbolAddress((void**)&Wp, g_W);

    cudaFuncSetAttribute(gemm_qkv,   cudaFuncAttributeMaxDynamicSharedMemorySize, GSMEM);
    cudaFuncSetAttribute(gemm_out,   cudaFuncAttributeMaxDynamicSharedMemorySize, GSMEM);
    cudaFuncSetAttribute(attn_flash, cudaFuncAttributeMaxDynamicSharedMemorySize, ATTN_SMEM);

    prep<<<XBLKS + 4096, 256>>>((const float4*)x, (uint2*)Xp,
                                Wq, Wk, Wv, Wo, Wp);

    dim3 gqkv((EMBD / 128) * 3, MROWS / 128);   // (24, 64), z fastest
    gemm_qkv<<<gqkv, 256, GSMEM>>>(Xp, Wp, Qp, Kp, Vp);

    dim3 ga(SEQ / 128, BATCH * NHEAD);          // (16, 64)
    attn_flash<<<ga, 128, ATTN_SMEM>>>(Qp, Kp, Vp, Ap);

    dim3 go(EMBD / 128, MROWS / 128);
    gemm_out<<<go, 256, GSMEM>>>(Ap, Wp + 3 * (size_t)EMBD * EMBD, out);
}